// round 2
// baseline (speedup 1.0000x reference)
#include <cuda_runtime.h>
#include <cstdint>

#define B_ 8
#define C_ 16
#define H_ 224
#define W_ 224
#define T_ 8
#define N_ 5
#define NEGV (-1e30f)
#define NTOT (B_*C_*H_*W_)

// Scratch: xv = log1p(relu(x)), computed once, reused by all 8 trees per plane.
__device__ float g_xv[NTOT];

__global__ void xv_kernel(const float* __restrict__ x) {
    int n4 = NTOT / 4;
    for (int i = blockIdx.x * blockDim.x + threadIdx.x; i < n4;
         i += gridDim.x * blockDim.x) {
        float4 v = reinterpret_cast<const float4*>(x)[i];
        v.x = log1pf(fmaxf(v.x, 0.f));
        v.y = log1pf(fmaxf(v.y, 0.f));
        v.z = log1pf(fmaxf(v.z, 0.f));
        v.w = log1pf(fmaxf(v.w, 0.f));
        reinterpret_cast<float4*>(g_xv)[i] = v;
    }
}

struct Forest { int par[T_][N_]; };

// cummax update for a 28-lane x 4-col chunk with an incoming carry
// (carry = inclusive 2D-cummax total of everything left of this warp's
// columns, through the CURRENT row; NEGV for the leftmost warp).
// M <- cummax_w( max(M, v) ) with carry folded in at the left edge.
__device__ __forceinline__ void scan_update(const float v[4], float M[4],
                                            int lane, float carry) {
    const unsigned FULL = 0xffffffffu;
    float u[4];
#pragma unroll
    for (int l = 0; l < 4; l++) u[l] = fmaxf(M[l], v[l]);
    u[1] = fmaxf(u[1], u[0]);
    u[2] = fmaxf(u[2], u[1]);
    u[3] = fmaxf(u[3], u[2]);
    float tot = u[3];
    if (lane == 0) tot = fmaxf(tot, carry);
#pragma unroll
    for (int d = 1; d < 32; d <<= 1) {
        float o = __shfl_up_sync(FULL, tot, d);  // self for lane<d -> no-op
        tot = fmaxf(tot, o);
    }
    float excl = __shfl_up_sync(FULL, tot, 1);
    if (lane == 0) excl = carry;
#pragma unroll
    for (int l = 0; l < 4; l++) M[l] = fmaxf(u[l], excl);
}

__global__ void __launch_bounds__(64)
forest_kernel(const float* __restrict__ alphas, float* __restrict__ out, Forest f) {
    const unsigned FULL = 0xffffffffu;
    __shared__ float s_tot[H_][4];   // warp0's per-row inclusive totals, nodes 1..4
    __shared__ unsigned s_prog;      // warp0's completed-row count
    __shared__ float s_runmax;

    int blk = blockIdx.x;
    int t = blk & 7;
    int c = (blk >> 3) & 15;
    int b = blk >> 7;
    int warp = threadIdx.x >> 5;
    int lane = threadIdx.x & 31;

    if (threadIdx.x == 0) s_prog = 0u;
    __syncthreads();

    unsigned prog_addr = (unsigned)__cvta_generic_to_shared(&s_prog);

    const float* plane = g_xv + (size_t)(b * C_ + c) * (H_ * W_);
    const float* rowp = plane + warp * 112 + lane * 4;

    float a[N_];
#pragma unroll
    for (int i = 0; i < N_; i++) a[i] = alphas[(t * N_ + i) * C_ + c];

    const int p2 = f.par[t][2], p3 = f.par[t][3], p4 = f.par[t][4];
    // p1 is always 0 (integers(0,1) == 0)

    // M[j]: inclusive 2D cummax of node j+1 over rows processed so far,
    // this warp's 112 columns (28 lanes x 4 cols).
    float M[4][4];
#pragma unroll
    for (int j = 0; j < 4; j++)
#pragma unroll
        for (int l = 0; l < 4; l++) M[j][l] = NEGV;

    // warp1: last received warp0 totals (= T(h-1)), for the ms column boundary.
    float prevT[4];
#pragma unroll
    for (int j = 0; j < 4; j++) prevT[j] = NEGV;

    float runmax = NEGV;
    const bool act = lane < 28;

    // Prefetch row 0
    float4 cur;
    if (act) cur = *reinterpret_cast<const float4*>(rowp);
    else     cur = make_float4(NEGV, NEGV, NEGV, NEGV);

    for (int h = 0; h < H_; h++) {
        // Prefetch next row (clamped; row 223's prefetch is discarded)
        int hn = (h + 1 < H_) ? h + 1 : h;
        float4 nxt;
        if (act) nxt = *reinterpret_cast<const float4*>(rowp + hn * W_);
        else     nxt = make_float4(NEGV, NEGV, NEGV, NEGV);

        float xv[4] = {cur.x, cur.y, cur.z, cur.w};

        // warp1: wait for warp0 to finish row h, then read its totals T(h).
        float carry[4];
        if (warp == 1) {
            unsigned p;
            do {
                asm volatile("ld.acquire.cta.shared.u32 %0, [%1];"
                             : "=r"(p) : "r"(prog_addr));
            } while (p < (unsigned)(h + 1));
#pragma unroll
            for (int j = 0; j < 4; j++) carry[j] = s_tot[h][j];
        } else {
#pragma unroll
            for (int j = 0; j < 4; j++) carry[j] = NEGV;
        }

        // Shifted previous-row M: ms[j][w] = M_old[j][w-1].
        // Left boundary: NEGV for warp0 (col 0), prevT (= T(h-1)) for warp1.
        float ms[4][4];
#pragma unroll
        for (int j = 0; j < 4; j++) {
            float up = __shfl_up_sync(FULL, M[j][3], 1);
            float bnd = (warp == 0) ? NEGV : prevT[j];
            ms[j][0] = (lane == 0) ? bnd : up;
            ms[j][1] = M[j][0];
            ms[j][2] = M[j][1];
            ms[j][3] = M[j][2];
        }
        if (warp == 1) {
#pragma unroll
            for (int j = 0; j < 4; j++) prevT[j] = carry[j];
        }

        float v[4];
        // ---- node 4 (no children possible) ----
#pragma unroll
        for (int l = 0; l < 4; l++) v[l] = xv[l] + a[4];
        scan_update(v, M[3], lane, carry[3]);

        // ---- node 3 (possible child: 4) ----
#pragma unroll
        for (int l = 0; l < 4; l++) v[l] = xv[l] + a[3];
        if (p4 == 3) {
#pragma unroll
            for (int l = 0; l < 4; l++) v[l] += ms[3][l];
        }
        scan_update(v, M[2], lane, carry[2]);

        // ---- node 2 (possible children: 3,4) ----
#pragma unroll
        for (int l = 0; l < 4; l++) v[l] = xv[l] + a[2];
        if (p3 == 2) {
#pragma unroll
            for (int l = 0; l < 4; l++) v[l] += ms[2][l];
        }
        if (p4 == 2) {
#pragma unroll
            for (int l = 0; l < 4; l++) v[l] += ms[3][l];
        }
        scan_update(v, M[1], lane, carry[1]);

        // ---- node 1 (possible children: 2,3,4) ----
#pragma unroll
        for (int l = 0; l < 4; l++) v[l] = xv[l] + a[1];
        if (p2 == 1) {
#pragma unroll
            for (int l = 0; l < 4; l++) v[l] += ms[1][l];
        }
        if (p3 == 1) {
#pragma unroll
            for (int l = 0; l < 4; l++) v[l] += ms[2][l];
        }
        if (p4 == 1) {
#pragma unroll
            for (int l = 0; l < 4; l++) v[l] += ms[3][l];
        }
        scan_update(v, M[0], lane, carry[0]);

        // warp0: publish this row's inclusive totals (lane 31 of M[j] holds
        // the full total: lanes 28-31 carry the prefix through lane 27).
        if (warp == 0 && lane == 31) {
#pragma unroll
            for (int j = 0; j < 4; j++) s_tot[h][j] = M[j][3];
            asm volatile("st.release.cta.shared.u32 [%0], %1;"
                         :: "r"(prog_addr), "r"((unsigned)(h + 1)) : "memory");
        }

        // ---- root node 0: node 1 is always a child ----
#pragma unroll
        for (int l = 0; l < 4; l++) v[l] = xv[l] + a[0] + ms[0][l];
        if (p2 == 0) {
#pragma unroll
            for (int l = 0; l < 4; l++) v[l] += ms[1][l];
        }
        if (p3 == 0) {
#pragma unroll
            for (int l = 0; l < 4; l++) v[l] += ms[2][l];
        }
        if (p4 == 0) {
#pragma unroll
            for (int l = 0; l < 4; l++) v[l] += ms[3][l];
        }
#pragma unroll
        for (int l = 0; l < 4; l++) runmax = fmaxf(runmax, v[l]);

        cur = nxt;
    }

#pragma unroll
    for (int d = 16; d; d >>= 1)
        runmax = fmaxf(runmax, __shfl_xor_sync(FULL, runmax, d));

    if (warp == 0 && lane == 0) s_runmax = runmax;
    __syncthreads();
    if (warp == 1 && lane == 0)
        out[(b * T_ + t) * C_ + c] = expm1f(fmaxf(runmax, s_runmax));
}

// ============================================================================
// Host: exact replication of np.random.default_rng(0) draws used by
// make_forest(): SeedSequence(0) -> PCG64 (XSL-RR 128/64) -> Generator
// .integers(0, i) (Lemire, buffered 32-bit path) for i = 1..4 per tree.
// ============================================================================

static inline uint32_t hashmix_(uint32_t v, uint32_t* hc) {
    v ^= *hc;
    *hc *= 0x931e8875u;   // MULT_A
    v *= *hc;
    v ^= v >> 16;
    return v;
}
static inline uint32_t mix_(uint32_t x, uint32_t y) {
    uint32_t r = x * 0xca01f9ddu - y * 0x4973f715u;  // MIX_MULT_L/R
    r ^= r >> 16;
    return r;
}

static void compute_forest(Forest* f) {
    // SeedSequence(0): entropy = [0]
    uint32_t pool[4];
    uint32_t hc = 0x43b0d7e5u;  // INIT_A
    for (int i = 0; i < 4; i++) pool[i] = hashmix_(0u, &hc);
    for (int s = 0; s < 4; s++)
        for (int d = 0; d < 4; d++)
            if (s != d) pool[d] = mix_(pool[d], hashmix_(pool[s], &hc));

    uint32_t hb = 0x8b51f9ddu;  // INIT_B
    uint32_t w32[8];
    for (int i = 0; i < 8; i++) {
        uint32_t dv = pool[i & 3];
        dv ^= hb;
        hb *= 0x58f38dedu;  // MULT_B
        dv *= hb;
        dv ^= dv >> 16;
        w32[i] = dv;
    }
    uint64_t val[4];
    for (int i = 0; i < 4; i++)
        val[i] = (uint64_t)w32[2 * i] | ((uint64_t)w32[2 * i + 1] << 32);

    typedef unsigned __int128 u128;
    const u128 MULT = ((u128)2549297995355413924ULL << 64) | 4865540595714422341ULL;
    u128 initstate = ((u128)val[0] << 64) | (u128)val[1];
    u128 inc = (((((u128)val[2] << 64) | (u128)val[3])) << 1) | 1;
    u128 state = inc;
    state += initstate;
    state = state * MULT + inc;

    int has32 = 0;
    uint32_t cached = 0;

    for (int t = 0; t < T_; t++) {
        f->par[t][0] = -1;
        f->par[t][1] = 0;  // integers(0,1): rng==0, no draw consumed
        for (int i = 2; i < N_; i++) {
            uint32_t rng = (uint32_t)i - 1u;
            uint32_t rng_excl = rng + 1u;
            uint64_t m;
            uint32_t leftover;
            for (;;) {
                uint32_t r32;
                if (has32) {
                    has32 = 0;
                    r32 = cached;
                } else {
                    state = state * MULT + inc;
                    uint64_t hi = (uint64_t)(state >> 64);
                    uint64_t lo = (uint64_t)state;
                    unsigned rot = (unsigned)(uint64_t)(state >> 122);
                    uint64_t x = hi ^ lo;
                    uint64_t o = (x >> rot) | (x << ((64u - rot) & 63u));
                    has32 = 1;
                    cached = (uint32_t)(o >> 32);
                    r32 = (uint32_t)o;
                }
                m = (uint64_t)r32 * (uint64_t)rng_excl;
                leftover = (uint32_t)m;
                if (leftover >= rng_excl) break;
                uint32_t thr = (0xFFFFFFFFu - rng) % rng_excl;
                if (leftover >= thr) break;
            }
            f->par[t][i] = (int)(uint32_t)(m >> 32);
        }
    }
}

extern "C" void kernel_launch(void* const* d_in, const int* in_sizes, int n_in,
                              void* d_out, int out_size) {
    const float* x = (const float*)d_in[0];
    const float* alphas = (const float*)d_in[1];
    float* out = (float*)d_out;

    Forest f;
    compute_forest(&f);

    xv_kernel<<<NTOT / 4 / 256, 256>>>(x);
    forest_kernel<<<B_ * C_ * T_, 64>>>(alphas, out, f);
}

// round 3
// speedup vs baseline: 1.9837x; 1.9837x over previous
#include <cuda_runtime.h>
#include <cstdint>

#define B_ 8
#define C_ 16
#define H_ 224
#define W_ 224
#define T_ 8
#define N_ 5
#define NEGV (-1e30f)
#define NTOT (B_*C_*H_*W_)

// Scratch: xv = log1p(relu(x)); padded by one row so the row-loop prefetch
// can read one row past the end unconditionally.
__device__ float g_xv[NTOT + W_];

__global__ void xv_kernel(const float* __restrict__ x) {
    int n4 = NTOT / 4;
    for (int i = blockIdx.x * blockDim.x + threadIdx.x; i < n4;
         i += gridDim.x * blockDim.x) {
        float4 v = reinterpret_cast<const float4*>(x)[i];
        v.x = log1pf(fmaxf(v.x, 0.f));
        v.y = log1pf(fmaxf(v.y, 0.f));
        v.z = log1pf(fmaxf(v.z, 0.f));
        v.w = log1pf(fmaxf(v.w, 0.f));
        reinterpret_cast<float4*>(g_xv)[i] = v;
    }
}

struct Forest { int par[T_][N_]; };

union F2U { float2 f; unsigned long long u; };
__device__ __forceinline__ float2 f2add(float2 a, float2 b) {
    F2U A, B, R; A.f = a; B.f = b;
    asm("add.rn.f32x2 %0, %1, %2;" : "=l"(R.u) : "l"(A.u), "l"(B.u));
    return R.f;
}

__global__ void __launch_bounds__(32)
forest_kernel(const float* __restrict__ alphas, float* __restrict__ out, Forest f) {
    const unsigned FULL = 0xffffffffu;
    int blk = blockIdx.x;
    int t = blk & 7;
    int c = (blk >> 3) & 15;
    int b = blk >> 7;
    int lane = threadIdx.x;
    const float* plane = g_xv + (size_t)(b * C_ + c) * (H_ * W_);

    float2 a2[N_];
#pragma unroll
    for (int i = 0; i < N_; i++) {
        float av = alphas[(t * N_ + i) * C_ + c];
        a2[i] = make_float2(av, av);
    }

    const int p2 = f.par[t][2], p3 = f.par[t][3], p4 = f.par[t][4];
    // p1 is always 0 (integers(0,1) == 0)

    // M[j]: inclusive 2D cummax of node j+1 over rows processed so far.
    // 28 active lanes x 8 columns.
    float M[4][8];
#pragma unroll
    for (int j = 0; j < 4; j++)
#pragma unroll
        for (int l = 0; l < 8; l++) M[j][l] = NEGV;

    float runmax = NEGV;
    const bool act = lane < 28;
    const float* rowp = plane + lane * 8;

    // Prefetch row 0
    float4 c0, c1;
    if (act) {
        c0 = *reinterpret_cast<const float4*>(rowp);
        c1 = *reinterpret_cast<const float4*>(rowp + 4);
    } else {
        c0 = make_float4(NEGV, NEGV, NEGV, NEGV);
        c1 = c0;
    }

#pragma unroll 2
    for (int h = 0; h < H_; h++) {
        // Unconditional prefetch of next row (scratch is padded by one row).
        const float* nrp = rowp + W_;
        float4 n0, n1;
        if (act) {
            n0 = *reinterpret_cast<const float4*>(nrp);
            n1 = *reinterpret_cast<const float4*>(nrp + 4);
        } else {
            n0 = make_float4(NEGV, NEGV, NEGV, NEGV);
            n1 = n0;
        }

        float xv[8] = {c0.x, c0.y, c0.z, c0.w, c1.x, c1.y, c1.z, c1.w};
        float2* xv2 = reinterpret_cast<float2*>(xv);

        // Boundary values for the shifted previous-row state:
        // bnd[j] = M_old[j] at the last column of the lane to the left.
        float bnd[4];
#pragma unroll
        for (int j = 0; j < 4; j++) {
            float up = __shfl_up_sync(FULL, M[j][7], 1);
            bnd[j] = (lane == 0) ? NEGV : up;
        }

        // ---- Stage A: build v for all nodes from M_old (shifted) ----
        float v4[8], v3[8], v2a[8], v1[8], r0[8];
#pragma unroll
        for (int k = 0; k < 4; k++) {
            reinterpret_cast<float2*>(v4)[k]  = f2add(xv2[k], a2[4]);
            reinterpret_cast<float2*>(v3)[k]  = f2add(xv2[k], a2[3]);
            reinterpret_cast<float2*>(v2a)[k] = f2add(xv2[k], a2[2]);
            reinterpret_cast<float2*>(v1)[k]  = f2add(xv2[k], a2[1]);
            reinterpret_cast<float2*>(r0)[k]  = f2add(xv2[k], a2[0]);
        }
        // ms[j][l] = (l==0 ? bnd[j] : M[j][l-1])
        if (p4 == 3) {
            v3[0] += bnd[3];
#pragma unroll
            for (int l = 1; l < 8; l++) v3[l] += M[3][l - 1];
        }
        if (p3 == 2) {
            v2a[0] += bnd[2];
#pragma unroll
            for (int l = 1; l < 8; l++) v2a[l] += M[2][l - 1];
        }
        if (p4 == 2) {
            v2a[0] += bnd[3];
#pragma unroll
            for (int l = 1; l < 8; l++) v2a[l] += M[3][l - 1];
        }
        if (p2 == 1) {
            v1[0] += bnd[1];
#pragma unroll
            for (int l = 1; l < 8; l++) v1[l] += M[1][l - 1];
        }
        if (p3 == 1) {
            v1[0] += bnd[2];
#pragma unroll
            for (int l = 1; l < 8; l++) v1[l] += M[2][l - 1];
        }
        if (p4 == 1) {
            v1[0] += bnd[3];
#pragma unroll
            for (int l = 1; l < 8; l++) v1[l] += M[3][l - 1];
        }
        // root: node 1 is always a child
        r0[0] += bnd[0];
#pragma unroll
        for (int l = 1; l < 8; l++) r0[l] += M[0][l - 1];
        if (p2 == 0) {
            r0[0] += bnd[1];
#pragma unroll
            for (int l = 1; l < 8; l++) r0[l] += M[1][l - 1];
        }
        if (p3 == 0) {
            r0[0] += bnd[2];
#pragma unroll
            for (int l = 1; l < 8; l++) r0[l] += M[2][l - 1];
        }
        if (p4 == 0) {
            r0[0] += bnd[3];
#pragma unroll
            for (int l = 1; l < 8; l++) r0[l] += M[3][l - 1];
        }
#pragma unroll
        for (int l = 0; l < 8; l++) runmax = fmaxf(runmax, r0[l]);

        // ---- Stage B: in-place chunk prefix max on each node's v ----
#pragma unroll
        for (int l = 1; l < 8; l++) {
            v1[l]  = fmaxf(v1[l],  v1[l - 1]);
            v2a[l] = fmaxf(v2a[l], v2a[l - 1]);
            v3[l]  = fmaxf(v3[l],  v3[l - 1]);
            v4[l]  = fmaxf(v4[l],  v4[l - 1]);
        }

        // ---- Stage C: interleaved exclusive warp scan over chunk totals.
        // Row-local (v only) — independent across rows, so consecutive
        // rows' SHFL chains pipeline. Exclusive: shift first, then scan.
        float ex[4];
        {
            float e0 = __shfl_up_sync(FULL, v1[7], 1);
            float e1 = __shfl_up_sync(FULL, v2a[7], 1);
            float e2 = __shfl_up_sync(FULL, v3[7], 1);
            float e3 = __shfl_up_sync(FULL, v4[7], 1);
            if (lane == 0) { e0 = NEGV; e1 = NEGV; e2 = NEGV; e3 = NEGV; }
#pragma unroll
            for (int d = 1; d < 32; d <<= 1) {
                float o0 = __shfl_up_sync(FULL, e0, d);
                float o1 = __shfl_up_sync(FULL, e1, d);
                float o2 = __shfl_up_sync(FULL, e2, d);
                float o3 = __shfl_up_sync(FULL, e3, d);
                e0 = fmaxf(e0, o0);
                e1 = fmaxf(e1, o1);
                e2 = fmaxf(e2, o2);
                e3 = fmaxf(e3, o3);
            }
            ex[0] = e0; ex[1] = e1; ex[2] = e2; ex[3] = e3;
        }

        // ---- Stage D: elementwise M update (the only cross-row carry) ----
#pragma unroll
        for (int l = 0; l < 8; l++) {
            M[0][l] = fmaxf(M[0][l], fmaxf(v1[l],  ex[0]));
            M[1][l] = fmaxf(M[1][l], fmaxf(v2a[l], ex[1]));
            M[2][l] = fmaxf(M[2][l], fmaxf(v3[l],  ex[2]));
            M[3][l] = fmaxf(M[3][l], fmaxf(v4[l],  ex[3]));
        }

        c0 = n0; c1 = n1;
        rowp = nrp;
    }

#pragma unroll
    for (int d = 16; d; d >>= 1)
        runmax = fmaxf(runmax, __shfl_xor_sync(FULL, runmax, d));
    if (lane == 0)
        out[(b * T_ + t) * C_ + c] = expm1f(runmax);
}

// ============================================================================
// Host: exact replication of np.random.default_rng(0) draws used by
// make_forest(): SeedSequence(0) -> PCG64 (XSL-RR 128/64) -> Generator
// .integers(0, i) (Lemire, buffered 32-bit path) for i = 1..4 per tree.
// ============================================================================

static inline uint32_t hashmix_(uint32_t v, uint32_t* hc) {
    v ^= *hc;
    *hc *= 0x931e8875u;   // MULT_A
    v *= *hc;
    v ^= v >> 16;
    return v;
}
static inline uint32_t mix_(uint32_t x, uint32_t y) {
    uint32_t r = x * 0xca01f9ddu - y * 0x4973f715u;  // MIX_MULT_L/R
    r ^= r >> 16;
    return r;
}

static void compute_forest(Forest* f) {
    uint32_t pool[4];
    uint32_t hc = 0x43b0d7e5u;  // INIT_A
    for (int i = 0; i < 4; i++) pool[i] = hashmix_(0u, &hc);
    for (int s = 0; s < 4; s++)
        for (int d = 0; d < 4; d++)
            if (s != d) pool[d] = mix_(pool[d], hashmix_(pool[s], &hc));

    uint32_t hb = 0x8b51f9ddu;  // INIT_B
    uint32_t w32[8];
    for (int i = 0; i < 8; i++) {
        uint32_t dv = pool[i & 3];
        dv ^= hb;
        hb *= 0x58f38dedu;  // MULT_B
        dv *= hb;
        dv ^= dv >> 16;
        w32[i] = dv;
    }
    uint64_t val[4];
    for (int i = 0; i < 4; i++)
        val[i] = (uint64_t)w32[2 * i] | ((uint64_t)w32[2 * i + 1] << 32);

    typedef unsigned __int128 u128;
    const u128 MULT = ((u128)2549297995355413924ULL << 64) | 4865540595714422341ULL;
    u128 initstate = ((u128)val[0] << 64) | (u128)val[1];
    u128 inc = (((((u128)val[2] << 64) | (u128)val[3])) << 1) | 1;
    u128 state = inc;
    state += initstate;
    state = state * MULT + inc;

    int has32 = 0;
    uint32_t cached = 0;

    for (int t = 0; t < T_; t++) {
        f->par[t][0] = -1;
        f->par[t][1] = 0;  // integers(0,1): rng==0, no draw consumed
        for (int i = 2; i < N_; i++) {
            uint32_t rng = (uint32_t)i - 1u;
            uint32_t rng_excl = rng + 1u;
            uint64_t m;
            uint32_t leftover;
            for (;;) {
                uint32_t r32;
                if (has32) {
                    has32 = 0;
                    r32 = cached;
                } else {
                    state = state * MULT + inc;
                    uint64_t hi = (uint64_t)(state >> 64);
                    uint64_t lo = (uint64_t)state;
                    unsigned rot = (unsigned)(uint64_t)(state >> 122);
                    uint64_t x = hi ^ lo;
                    uint64_t o = (x >> rot) | (x << ((64u - rot) & 63u));
                    has32 = 1;
                    cached = (uint32_t)(o >> 32);
                    r32 = (uint32_t)o;
                }
                m = (uint64_t)r32 * (uint64_t)rng_excl;
                leftover = (uint32_t)m;
                if (leftover >= rng_excl) break;
                uint32_t thr = (0xFFFFFFFFu - rng) % rng_excl;
                if (leftover >= thr) break;
            }
            f->par[t][i] = (int)(uint32_t)(m >> 32);
        }
    }
}

extern "C" void kernel_launch(void* const* d_in, const int* in_sizes, int n_in,
                              void* d_out, int out_size) {
    const float* x = (const float*)d_in[0];
    const float* alphas = (const float*)d_in[1];
    float* out = (float*)d_out;

    Forest f;
    compute_forest(&f);

    xv_kernel<<<NTOT / 4 / 256, 256>>>(x);
    forest_kernel<<<B_ * C_ * T_, 32>>>(alphas, out, f);
}